// round 6
// baseline (speedup 1.0000x reference)
#include <cuda_runtime.h>

#define VV 100000
#define DD 128
#define MM 200
#define HOPS 3
#define NKS 37                 // k-split blocks; 37*2*2 = 148 = one wave
#define KSTEPS 3125            // 100000 / 32
#define MPAD 256

// ---------------- scratch (allocation-free) ----------------
__device__ float g_qd[DD];
__device__ float g_A2[MPAD * DD];   // memory @ Wa^T (split-K atomic accum)
__device__ float g_C2[MPAD * DD];   // memory @ Wc^T

__device__ __forceinline__ float warp_sum(float v) {
#pragma unroll
    for (int o = 16; o > 0; o >>= 1) v += __shfl_xor_sync(0xffffffffu, v, o);
    return v;
}

__device__ __forceinline__ unsigned f2tf32(float x) {
    unsigned r;
    asm("cvt.rna.tf32.f32 %0, %1;" : "=r"(r) : "f"(x));
    return r;
}

// x ~= hi + lo, both tf32-representable (3xTF32 scheme)
__device__ __forceinline__ void split3(float x, unsigned& hi, unsigned& lo) {
    hi = f2tf32(x);
    lo = f2tf32(x - __uint_as_float(hi));
}

__device__ __forceinline__ void mma8(float* c, const unsigned* a, unsigned b0, unsigned b1) {
    asm volatile(
        "mma.sync.aligned.m16n8k8.row.col.f32.tf32.tf32.f32 "
        "{%0,%1,%2,%3},{%4,%5,%6,%7},{%8,%9},{%0,%1,%2,%3};"
        : "+f"(c[0]), "+f"(c[1]), "+f"(c[2]), "+f"(c[3])
        : "r"(a[0]), "r"(a[1]), "r"(a[2]), "r"(a[3]), "r"(b0), "r"(b1));
}

__global__ void k_init() {
    int i = blockIdx.x * blockDim.x + threadIdx.x;
    if (i < MPAD * DD) { g_A2[i] = 0.f; g_C2[i] = 0.f; }
    if (i < DD) g_qd[i] = 0.f;
}

// ---------------- qd0 = question @ Wb^T (fp32 exact) ----------------
__global__ void __launch_bounds__(256) k_quesd(
    const float* __restrict__ Wb, const float* __restrict__ question) {
    __shared__ float sred[8];
    const int tid = threadIdx.x, lane = tid & 31, w = tid >> 5;
    const int r = blockIdx.x >> 1, half = blockIdx.x & 1;
    const float4* wr = (const float4*)(Wb + (size_t)r * VV + half * 50000);
    const float4* qv = (const float4*)(question + half * 50000);
    float acc = 0.f;
    for (int q = tid; q < 12500; q += 256) {
        float4 a = wr[q], b = qv[q];
        acc += a.x * b.x + a.y * b.y + a.z * b.z + a.w * b.w;
    }
    acc = warp_sum(acc);
    if (lane == 0) sred[w] = acc;
    __syncthreads();
    if (w == 0) {
        float x = (lane < 8) ? sred[lane] : 0.f;
        x = warp_sum(x);
        if (lane == 0) atomicAdd(&g_qd[r], x);
    }
}

// ---------------- A2/C2 GEMM: 3xTF32, static smem, register-staged pipeline ----
// grid (NKS, 2 n-halves, 2 matrices). Block 512 thr. Tile: M=256, N=64, K=32.
__global__ void __launch_bounds__(512, 1) k_gemm(
    const float* __restrict__ mem, const float* __restrict__ Wa,
    const float* __restrict__ Wc) {
    __shared__ float sA[256 * 36];     // 36864 B
    __shared__ float sB[64 * 36];      //  9216 B   (total 45 KB static)

    const int tid = threadIdx.x, lane = tid & 31, w = tid >> 5;
    const int gid = lane >> 2, tig = lane & 3;
    const int nh = blockIdx.y;
    const float* B = blockIdx.z ? Wc : Wa;
    float* G = blockIdx.z ? g_C2 : g_A2;
    const int wm = w & 7, wn = w >> 3;
    const int mb = wm * 32, nb = wn * 32;
    const int s0 = (int)blockIdx.x * KSTEPS / NKS;
    const int s1 = ((int)blockIdx.x + 1) * KSTEPS / NKS;

    // A-load coords: 4 float4/thread; B-load: 1 float4/thread
    const int am[4] = { (tid + 0) >> 3, (tid + 512) >> 3, (tid + 1024) >> 3, (tid + 1536) >> 3 };
    const int ac4 = (tid & 7) * 4;
    const int bn = tid >> 3;

    float acc[2][4][4];
#pragma unroll
    for (int mt = 0; mt < 2; mt++)
#pragma unroll
        for (int nt = 0; nt < 4; nt++)
#pragma unroll
            for (int j = 0; j < 4; j++) acc[mt][nt][j] = 0.f;

    float4 rA[4], rB;
    auto load_regs = [&](int s) {
        const int k0 = s * 32;
#pragma unroll
        for (int i = 0; i < 4; i++) {
            if (am[i] < MM)
                rA[i] = *(const float4*)(mem + (size_t)am[i] * VV + k0 + ac4);
            else
                rA[i] = make_float4(0.f, 0.f, 0.f, 0.f);
        }
        rB = *(const float4*)(B + (size_t)(nh * 64 + bn) * VV + k0 + ac4);
    };

    load_regs(s0);
    for (int s = s0; s < s1; s++) {
        __syncthreads();                       // consumers of prev step done
#pragma unroll
        for (int i = 0; i < 4; i++)
            *(float4*)(sA + am[i] * 36 + ac4) = rA[i];
        *(float4*)(sB + bn * 36 + ac4) = rB;
        __syncthreads();
        if (s + 1 < s1) load_regs(s + 1);      // LDGs overlap the MMA loop below

#pragma unroll
        for (int q = 0; q < 4; q++) {
            unsigned ah[2][4], al[2][4];
#pragma unroll
            for (int mt = 0; mt < 2; mt++) {
                const int r = mb + mt * 16 + gid;
                split3(sA[r * 36 + q * 8 + tig],            ah[mt][0], al[mt][0]);
                split3(sA[(r + 8) * 36 + q * 8 + tig],      ah[mt][1], al[mt][1]);
                split3(sA[r * 36 + q * 8 + tig + 4],        ah[mt][2], al[mt][2]);
                split3(sA[(r + 8) * 36 + q * 8 + tig + 4],  ah[mt][3], al[mt][3]);
            }
#pragma unroll
            for (int nt = 0; nt < 4; nt++) {
                const int n = nb + nt * 8 + gid;
                unsigned bh0, bl0, bh1, bl1;
                split3(sB[n * 36 + q * 8 + tig],     bh0, bl0);
                split3(sB[n * 36 + q * 8 + tig + 4], bh1, bl1);
#pragma unroll
                for (int mt = 0; mt < 2; mt++) {
                    mma8(acc[mt][nt], ah[mt], bl0, bl1);   // hi*lo
                    mma8(acc[mt][nt], al[mt], bh0, bh1);   // lo*hi
                    mma8(acc[mt][nt], ah[mt], bh0, bh1);   // hi*hi
                }
            }
        }
    }

    // split-K accumulate
#pragma unroll
    for (int mt = 0; mt < 2; mt++)
#pragma unroll
        for (int nt = 0; nt < 4; nt++) {
            const int r0 = mb + mt * 16 + gid;
            const int c0 = nh * 64 + nb + nt * 8 + tig * 2;
            atomicAdd(&G[r0 * DD + c0],           acc[mt][nt][0]);
            atomicAdd(&G[r0 * DD + c0 + 1],       acc[mt][nt][1]);
            atomicAdd(&G[(r0 + 8) * DD + c0],     acc[mt][nt][2]);
            atomicAdd(&G[(r0 + 8) * DD + c0 + 1], acc[mt][nt][3]);
        }
}

// ---------------- all 3 hops, single block (reads A2/C2 from L2) ----------------
__global__ void __launch_bounds__(512) k_hops(
    const float* __restrict__ tA, const float* __restrict__ tC) {
    __shared__ float sqd[DD];
    __shared__ float sl[256];
    __shared__ float sred[512];
    const int tid = threadIdx.x, lane = tid & 31, w = tid >> 5;
    if (tid < DD) sqd[tid] = g_qd[tid];
    __syncthreads();

    for (int h = 0; h < HOPS; h++) {
        // logits[m] = (A2[m]+tA[m]) . qd
        for (int m = w; m < MM; m += 16) {
            float acc = 0.f;
#pragma unroll
            for (int k = 0; k < 4; k++) {
                int d = lane + 32 * k;
                acc += (g_A2[m * DD + d] + tA[m * DD + d]) * sqd[d];
            }
            acc = warp_sum(acc);
            if (lane == 0) sl[m] = acc;
        }
        __syncthreads();
        sred[tid] = (tid < MM) ? sl[tid] : -3.4e38f;
        __syncthreads();
        for (int s = 256; s >= 1; s >>= 1) {
            if (tid < s) sred[tid] = fmaxf(sred[tid], sred[tid + s]);
            __syncthreads();
        }
        float mx = sred[0];
        __syncthreads();
        float e = (tid < MM) ? expf(sl[tid] - mx) : 0.f;
        sred[tid] = e;
        __syncthreads();
        for (int s = 256; s >= 1; s >>= 1) {
            if (tid < s) sred[tid] += sred[tid + s];
            __syncthreads();
        }
        float inv = 1.f / sred[0];
        __syncthreads();
        if (tid < MM) sl[tid] = e * inv;        // sl = P
        __syncthreads();
        // o[d] = qd[d] + sum_m P[m]*(C2[m][d]+tC[m][d])  (4-way m-split)
        {
            const int q = tid >> 7, d = tid & 127;
            float part = 0.f;
            for (int m = q * 50; m < q * 50 + 50; m++)
                part += sl[m] * (g_C2[m * DD + d] + tC[m * DD + d]);
            sred[tid] = part;
            __syncthreads();
            float o = 0.f;
            if (q == 0)
                o = sqd[d] + sred[d] + sred[d + 128] + sred[d + 256] + sred[d + 384];
            __syncthreads();
            if (q == 0) sqd[d] = o;
            __syncthreads();
        }
    }
    if (tid < DD) g_qd[tid] = sqd[tid];
}

// ---------------- out[v] = o . Wout[v] ----------------
__global__ void __launch_bounds__(256) k_out(
    const float* __restrict__ Wout, float* __restrict__ out) {
    const int lane = threadIdx.x & 31;
    const int gw = (blockIdx.x * 256 + threadIdx.x) >> 5;
    const int nw = (gridDim.x * 256) >> 5;
    float4 qv = *(const float4*)(&g_qd[lane * 4]);
    for (int r = gw; r < VV; r += nw) {
        float4 wv = ((const float4*)(Wout + (size_t)r * DD))[lane];
        float acc = qv.x * wv.x + qv.y * wv.y + qv.z * wv.z + qv.w * wv.w;
        acc = warp_sum(acc);
        if (lane == 0) out[r] = acc;
    }
}

extern "C" void kernel_launch(void* const* d_in, const int* in_sizes, int n_in,
                              void* d_out, int out_size) {
    const float* question = (const float*)d_in[0];
    const float* memory   = (const float*)d_in[1];
    const float* Wa       = (const float*)d_in[2];
    const float* Wb       = (const float*)d_in[3];
    const float* Wc       = (const float*)d_in[4];
    const float* Wout     = (const float*)d_in[5];
    const float* tA       = (const float*)d_in[6];
    const float* tC       = (const float*)d_in[7];
    float* out = (float*)d_out;

    k_init<<<32, 1024>>>();
    k_quesd<<<DD * 2, 256>>>(Wb, question);
    k_gemm<<<dim3(NKS, 2, 2), 512>>>(memory, Wa, Wc);
    k_hops<<<1, 512>>>(tA, tC);
    k_out<<<592, 256>>>(Wout, out);
}

// round 7
// speedup vs baseline: 1.3099x; 1.3099x over previous
#include <cuda_runtime.h>

#define VV 100000
#define DD 128
#define MM 200
#define HOPS 3
#define NKS 74                 // k-split blocks; 74*2 = 148 = one wave
#define KSTEPS 3125            // 100000 / 32
#define MPAD 256

// ---------------- scratch (allocation-free) ----------------
__device__ float g_qd[DD];
__device__ float g_A2[MPAD * DD];   // tA + memory @ Wa^T (split-K atomic accum)
__device__ float g_C2[MPAD * DD];   // tC + memory @ Wc^T

__device__ __forceinline__ float warp_sum(float v) {
#pragma unroll
    for (int o = 16; o > 0; o >>= 1) v += __shfl_xor_sync(0xffffffffu, v, o);
    return v;
}

__device__ __forceinline__ unsigned f2tf32(float x) {
    unsigned r;
    asm("cvt.rna.tf32.f32 %0, %1;" : "=r"(r) : "f"(x));
    return r;
}

__device__ __forceinline__ void mma8(float* c, const unsigned* a, unsigned b0, unsigned b1) {
    asm volatile(
        "mma.sync.aligned.m16n8k8.row.col.f32.tf32.tf32.f32 "
        "{%0,%1,%2,%3},{%4,%5,%6,%7},{%8,%9},{%0,%1,%2,%3};"
        : "+f"(c[0]), "+f"(c[1]), "+f"(c[2]), "+f"(c[3])
        : "r"(a[0]), "r"(a[1]), "r"(a[2]), "r"(a[3]), "r"(b0), "r"(b1));
}

// swizzled smem index for element (r, k) in a 32-wide tile
__device__ __forceinline__ int swz(int r, int k) {
    return r * 32 + (k ^ ((r & 7) << 2));
}

// k_init: fold temporal matrices into the accumulators (reset every replay)
__global__ void k_init(const float* __restrict__ tA, const float* __restrict__ tC) {
    int i = blockIdx.x * blockDim.x + threadIdx.x;
    if (i < MPAD * DD) {
        g_A2[i] = (i < MM * DD) ? tA[i] : 0.f;
        g_C2[i] = (i < MM * DD) ? tC[i] : 0.f;
    }
    if (i < DD) g_qd[i] = 0.f;
}

// ---------------- qd0 = question @ Wb^T (fp32 exact) ----------------
__global__ void __launch_bounds__(256) k_quesd(
    const float* __restrict__ Wb, const float* __restrict__ question) {
    __shared__ float sred[8];
    const int tid = threadIdx.x, lane = tid & 31, w = tid >> 5;
    const int r = blockIdx.x >> 1, half = blockIdx.x & 1;
    const float4* wr = (const float4*)(Wb + (size_t)r * VV + half * 50000);
    const float4* qv = (const float4*)(question + half * 50000);
    float acc = 0.f;
    for (int q = tid; q < 12500; q += 256) {
        float4 a = wr[q], b = qv[q];
        acc += a.x * b.x + a.y * b.y + a.z * b.z + a.w * b.w;
    }
    acc = warp_sum(acc);
    if (lane == 0) sred[w] = acc;
    __syncthreads();
    if (w == 0) {
        float x = (lane < 8) ? sred[lane] : 0.f;
        x = warp_sum(x);
        if (lane == 0) atomicAdd(&g_qd[r], x);
    }
}

// ---------------- A2/C2 GEMM: 1xTF32, loader-side cvt, swizzled 48KB smem ----
// grid (NKS, 2 n-halves). Block 512. Tile M=256, N=64, K=32. Both matrices/block.
__global__ void __launch_bounds__(512, 1) k_gemm(
    const float* __restrict__ mem, const float* __restrict__ Wa,
    const float* __restrict__ Wc) {
    __shared__ unsigned sA[256 * 32];   // 32 KB
    __shared__ unsigned sBa[64 * 32];   //  8 KB
    __shared__ unsigned sBc[64 * 32];   //  8 KB  (total 48 KB exactly)

    const int tid = threadIdx.x, lane = tid & 31, w = tid >> 5;
    const int gid = lane >> 2, tig = lane & 3;
    const int nh = blockIdx.y;
    const int wm = w & 7, wn = w >> 3;
    const int mb = wm * 32, nb = wn * 32;
    const int s0 = (int)blockIdx.x * KSTEPS / NKS;
    const int s1 = ((int)blockIdx.x + 1) * KSTEPS / NKS;

    const int am[4] = { (tid + 0) >> 3, (tid + 512) >> 3, (tid + 1024) >> 3, (tid + 1536) >> 3 };
    const int ac4 = (tid & 7) * 4;
    const int bn = tid >> 3;

    float accA[2][4][4], accC[2][4][4];
#pragma unroll
    for (int mt = 0; mt < 2; mt++)
#pragma unroll
        for (int nt = 0; nt < 4; nt++)
#pragma unroll
            for (int j = 0; j < 4; j++) { accA[mt][nt][j] = 0.f; accC[mt][nt][j] = 0.f; }

    float4 rA[4], rBa, rBc;
    auto load_regs = [&](int s) {
        const int k0 = s * 32;
#pragma unroll
        for (int i = 0; i < 4; i++) {
            if (am[i] < MM)
                rA[i] = *(const float4*)(mem + (size_t)am[i] * VV + k0 + ac4);
            else
                rA[i] = make_float4(0.f, 0.f, 0.f, 0.f);
        }
        rBa = *(const float4*)(Wa + (size_t)(nh * 64 + bn) * VV + k0 + ac4);
        rBc = *(const float4*)(Wc + (size_t)(nh * 64 + bn) * VV + k0 + ac4);
    };
    auto cvt4 = [&](float4 v) {
        uint4 u;
        u.x = f2tf32(v.x); u.y = f2tf32(v.y); u.z = f2tf32(v.z); u.w = f2tf32(v.w);
        return u;
    };

    load_regs(s0);
    for (int s = s0; s < s1; s++) {
        __syncthreads();
#pragma unroll
        for (int i = 0; i < 4; i++)
            *(uint4*)(sA + swz(am[i], ac4)) = cvt4(rA[i]);
        *(uint4*)(sBa + swz(bn, ac4)) = cvt4(rBa);
        *(uint4*)(sBc + swz(bn, ac4)) = cvt4(rBc);
        __syncthreads();
        if (s + 1 < s1) load_regs(s + 1);   // LDGs overlap MMA loop

#pragma unroll
        for (int q = 0; q < 4; q++) {
            const int c0 = q * 8 + tig;
            unsigned a[2][4];
#pragma unroll
            for (int mt = 0; mt < 2; mt++) {
                const int r = mb + mt * 16 + gid;
                a[mt][0] = sA[swz(r, c0)];
                a[mt][1] = sA[swz(r + 8, c0)];
                a[mt][2] = sA[swz(r, c0 + 4)];
                a[mt][3] = sA[swz(r + 8, c0 + 4)];
            }
#pragma unroll
            for (int nt = 0; nt < 4; nt++) {
                const int n = nb + nt * 8 + gid;
                unsigned ba0 = sBa[swz(n, c0)], ba1 = sBa[swz(n, c0 + 4)];
                unsigned bc0 = sBc[swz(n, c0)], bc1 = sBc[swz(n, c0 + 4)];
#pragma unroll
                for (int mt = 0; mt < 2; mt++) {
                    mma8(accA[mt][nt], a[mt], ba0, ba1);
                    mma8(accC[mt][nt], a[mt], bc0, bc1);
                }
            }
        }
    }

    // split-K accumulate (on top of tA/tC baseline from k_init)
#pragma unroll
    for (int mt = 0; mt < 2; mt++)
#pragma unroll
        for (int nt = 0; nt < 4; nt++) {
            const int r0 = mb + mt * 16 + gid;
            const int c0 = nh * 64 + nb + nt * 8 + tig * 2;
            atomicAdd(&g_A2[r0 * DD + c0],           accA[mt][nt][0]);
            atomicAdd(&g_A2[r0 * DD + c0 + 1],       accA[mt][nt][1]);
            atomicAdd(&g_A2[(r0 + 8) * DD + c0],     accA[mt][nt][2]);
            atomicAdd(&g_A2[(r0 + 8) * DD + c0 + 1], accA[mt][nt][3]);
            atomicAdd(&g_C2[r0 * DD + c0],           accC[mt][nt][0]);
            atomicAdd(&g_C2[r0 * DD + c0 + 1],       accC[mt][nt][1]);
            atomicAdd(&g_C2[(r0 + 8) * DD + c0],     accC[mt][nt][2]);
            atomicAdd(&g_C2[(r0 + 8) * DD + c0 + 1], accC[mt][nt][3]);
        }
}

// ---------------- 3 hops, single block, At register-cached ----------------
__global__ void __launch_bounds__(512) k_hops() {
    __shared__ float sqd[DD];
    __shared__ float sP[256];
    __shared__ float sred[512];
    const int tid = threadIdx.x, lane = tid & 31, w = tid >> 5;
    const int mbase = w * 13;                 // warp-owned A rows (13 each)

    // register cache of At (independent coalesced loads, done once)
    float ra[13][4];
#pragma unroll
    for (int i = 0; i < 13; i++) {
        const int m = mbase + i;
#pragma unroll
        for (int k = 0; k < 4; k++)
            ra[i][k] = (m < MM) ? g_A2[m * DD + lane + 32 * k] : 0.f;
    }
    if (tid < DD) sqd[tid] = g_qd[tid];
    __syncthreads();

    for (int h = 0; h < HOPS; h++) {
        // logits from registers
        float q0 = sqd[lane], q1 = sqd[lane + 32], q2 = sqd[lane + 64], q3 = sqd[lane + 96];
#pragma unroll
        for (int i = 0; i < 13; i++) {
            const int m = mbase + i;
            float acc = ra[i][0] * q0 + ra[i][1] * q1 + ra[i][2] * q2 + ra[i][3] * q3;
            acc = warp_sum(acc);
            if (lane == 0 && m < MM) sP[m] = acc;
        }
        __syncthreads();
        // softmax over 200
        sred[tid] = (tid < MM) ? sP[tid] : -3.4e38f;
        __syncthreads();
        for (int s = 256; s >= 1; s >>= 1) {
            if (tid < s) sred[tid] = fmaxf(sred[tid], sred[tid + s]);
            __syncthreads();
        }
        float mx = sred[0];
        __syncthreads();
        float e = (tid < MM) ? expf(sP[tid] - mx) : 0.f;
        sred[tid] = e;
        __syncthreads();
        for (int s = 256; s >= 1; s >>= 1) {
            if (tid < s) sred[tid] += sred[tid + s];
            __syncthreads();
        }
        float inv = 1.f / sred[0];
        __syncthreads();
        if (tid < MM) sP[tid] = e * inv;
        __syncthreads();
        // o[d] = qd[d] + sum_m P[m]*C2[m][d]  (4-way m-split, L2-burst reads)
        {
            const int q = tid >> 7, d = tid & 127;
            float part = 0.f;
#pragma unroll 10
            for (int m = q * 50; m < q * 50 + 50; m++)
                part += sP[m] * g_C2[m * DD + d];
            sred[tid] = part;
            __syncthreads();
            float o = 0.f;
            if (q == 0)
                o = sqd[d] + sred[d] + sred[d + 128] + sred[d + 256] + sred[d + 384];
            __syncthreads();
            if (q == 0) sqd[d] = o;
            __syncthreads();
        }
    }
    if (tid < DD) g_qd[tid] = sqd[tid];
}

// ---------------- out[v] = o . Wout[v] ----------------
__global__ void __launch_bounds__(256) k_out(
    const float* __restrict__ Wout, float* __restrict__ out) {
    const int lane = threadIdx.x & 31;
    const int gw = (blockIdx.x * 256 + threadIdx.x) >> 5;
    const int nw = (gridDim.x * 256) >> 5;
    float4 qv = *(const float4*)(&g_qd[lane * 4]);
    for (int r = gw; r < VV; r += nw) {
        float4 wv = ((const float4*)(Wout + (size_t)r * DD))[lane];
        float acc = qv.x * wv.x + qv.y * wv.y + qv.z * wv.z + qv.w * wv.w;
        acc = warp_sum(acc);
        if (lane == 0) out[r] = acc;
    }
}

extern "C" void kernel_launch(void* const* d_in, const int* in_sizes, int n_in,
                              void* d_out, int out_size) {
    const float* question = (const float*)d_in[0];
    const float* memory   = (const float*)d_in[1];
    const float* Wa       = (const float*)d_in[2];
    const float* Wb       = (const float*)d_in[3];
    const float* Wc       = (const float*)d_in[4];
    const float* Wout     = (const float*)d_in[5];
    const float* tA       = (const float*)d_in[6];
    const float* tC       = (const float*)d_in[7];
    float* out = (float*)d_out;

    k_init<<<32, 1024>>>(tA, tC);
    k_gemm<<<dim3(NKS, 2), 512>>>(memory, Wa, Wc);
    k_quesd<<<DD * 2, 256>>>(Wb, question);
    k_hops<<<1, 512>>>();
    k_out<<<592, 256>>>(Wout, out);
}

// round 9
// speedup vs baseline: 2.0386x; 1.5563x over previous
#include <cuda_runtime.h>

#define VV 100000
#define DD 128
#define MM 200
#define HOPS 3
#define NKS 74                 // k-split blocks; 74*2 = 148 = one wave
#define KSTEPS 3125            // 100000 / 32
#define MPAD 256

#define SAF 8192               // A-stage floats (256*32)
#define SBF 2048               // B-stage floats (64*32)
#define STAGEF (SAF + 2*SBF)   // 12288 floats = 48KB per stage
#define GSMEM (2 * STAGEF * 4) // 96KB dynamic

// ---------------- scratch (allocation-free) ----------------
__device__ float g_qd[DD];
__device__ float g_A2[MPAD * DD];   // tA + memory @ Wa^T (split-K atomic accum)
__device__ float g_C2[MPAD * DD];   // tC + memory @ Wc^T

__device__ __forceinline__ float warp_sum(float v) {
#pragma unroll
    for (int o = 16; o > 0; o >>= 1) v += __shfl_xor_sync(0xffffffffu, v, o);
    return v;
}

__device__ __forceinline__ unsigned f2tf32(float x) {
    unsigned r;
    asm("cvt.rna.tf32.f32 %0, %1;" : "=r"(r) : "f"(x));
    return r;
}

__device__ __forceinline__ void mma8(float* c, const unsigned* a, unsigned b0, unsigned b1) {
    asm volatile(
        "mma.sync.aligned.m16n8k8.row.col.f32.tf32.tf32.f32 "
        "{%0,%1,%2,%3},{%4,%5,%6,%7},{%8,%9},{%0,%1,%2,%3};"
        : "+f"(c[0]), "+f"(c[1]), "+f"(c[2]), "+f"(c[3])
        : "r"(a[0]), "r"(a[1]), "r"(a[2]), "r"(a[3]), "r"(b0), "r"(b1));
}

__device__ __forceinline__ void cpa16(unsigned saddr, const void* g) {
    asm volatile("cp.async.ca.shared.global [%0], [%1], 16;\n"
                 :: "r"(saddr), "l"(g));
}

// swizzled smem index for element (r, k) in a 32-wide tile (16B-granular XOR)
__device__ __forceinline__ int swz(int r, int k) {
    return r * 32 + (k ^ ((r & 7) << 2));
}

// fold temporal matrices into the accumulators (reset every replay)
__global__ void k_init(const float* __restrict__ tA, const float* __restrict__ tC) {
    int i = blockIdx.x * blockDim.x + threadIdx.x;
    if (i < MPAD * DD) {
        g_A2[i] = (i < MM * DD) ? tA[i] : 0.f;
        g_C2[i] = (i < MM * DD) ? tC[i] : 0.f;
    }
    if (i < DD) g_qd[i] = 0.f;
}

// ---------------- qd0 = question @ Wb^T (fp32 exact) ----------------
__global__ void __launch_bounds__(256) k_quesd(
    const float* __restrict__ Wb, const float* __restrict__ question) {
    __shared__ float sred[8];
    const int tid = threadIdx.x, lane = tid & 31, w = tid >> 5;
    const int r = blockIdx.x >> 1, half = blockIdx.x & 1;
    const float4* wr = (const float4*)(Wb + (size_t)r * VV + half * 50000);
    const float4* qv = (const float4*)(question + half * 50000);
    float acc = 0.f;
    for (int q = tid; q < 12500; q += 256) {
        float4 a = wr[q], b = qv[q];
        acc += a.x * b.x + a.y * b.y + a.z * b.z + a.w * b.w;
    }
    acc = warp_sum(acc);
    if (lane == 0) sred[w] = acc;
    __syncthreads();
    if (w == 0) {
        float x = (lane < 8) ? sred[lane] : 0.f;
        x = warp_sum(x);
        if (lane == 0) atomicAdd(&g_qd[r], x);
    }
}

// ---------------- A2/C2 GEMM: 1xTF32, cp.async double-buffered ----------------
// grid (NKS, 2 n-halves). Block 512. Tile M=256, N=64, K=32. Both matrices/block.
__global__ void __launch_bounds__(512, 1) k_gemm(
    const float* __restrict__ mem, const float* __restrict__ Wa,
    const float* __restrict__ Wc) {
    extern __shared__ float dsm[];

    const int tid = threadIdx.x, lane = tid & 31, w = tid >> 5;
    const int gid = lane >> 2, tig = lane & 3;
    const int nh = blockIdx.y;
    const int wm = w & 7, wn = w >> 3;
    const int mb = wm * 32, nb = wn * 32;
    const int s0 = (int)blockIdx.x * KSTEPS / NKS;
    const int s1 = ((int)blockIdx.x + 1) * KSTEPS / NKS;

    // load coords: A 4x16B/thread (rows clamped: rows>=200 garbage, never read);
    // B 1x16B/thread per matrix
    int amc[4];
#pragma unroll
    for (int i = 0; i < 4; i++) {
        int m = (tid + i * 512) >> 3;
        amc[i] = (m < MM) ? m : (MM - 1);
    }
    const int ac4 = (tid & 7) * 4;
    const int bn = tid >> 3;

    const unsigned sbase = (unsigned)__cvta_generic_to_shared(dsm);

    float accA[2][4][4], accC[2][4][4];
#pragma unroll
    for (int mt = 0; mt < 2; mt++)
#pragma unroll
        for (int nt = 0; nt < 4; nt++)
#pragma unroll
            for (int j = 0; j < 4; j++) { accA[mt][nt][j] = 0.f; accC[mt][nt][j] = 0.f; }

    auto issue = [&](int s, int p) {
        const int k0 = s * 32;
        const unsigned st = sbase + (unsigned)(p * STAGEF) * 4u;
#pragma unroll
        for (int i = 0; i < 4; i++)
            cpa16(st + (unsigned)swz(amc[i], ac4) * 4u,
                  mem + (size_t)amc[i] * VV + k0 + ac4);
        cpa16(st + (unsigned)(SAF + swz(bn, ac4)) * 4u,
              Wa + (size_t)(nh * 64 + bn) * VV + k0 + ac4);
        cpa16(st + (unsigned)(SAF + SBF + swz(bn, ac4)) * 4u,
              Wc + (size_t)(nh * 64 + bn) * VV + k0 + ac4);
        asm volatile("cp.async.commit_group;\n");
    };

    issue(s0, 0);
    for (int s = s0; s < s1; s++) {
        const int p = (s - s0) & 1;
        if (s + 1 < s1) {
            issue(s + 1, p ^ 1);                       // next stage in flight
            asm volatile("cp.async.wait_group 1;\n");  // current stage landed
        } else {
            asm volatile("cp.async.wait_group 0;\n");
        }
        __syncthreads();                               // all threads' copies visible

        const float* fA  = dsm + p * STAGEF;
        const float* fBa = fA + SAF;
        const float* fBc = fBa + SBF;
#pragma unroll
        for (int q = 0; q < 4; q++) {
            const int c0 = q * 8 + tig;
            unsigned a[2][4];
#pragma unroll
            for (int mt = 0; mt < 2; mt++) {
                const int r = mb + mt * 16 + gid;
                a[mt][0] = f2tf32(fA[swz(r, c0)]);
                a[mt][1] = f2tf32(fA[swz(r + 8, c0)]);
                a[mt][2] = f2tf32(fA[swz(r, c0 + 4)]);
                a[mt][3] = f2tf32(fA[swz(r + 8, c0 + 4)]);
            }
#pragma unroll
            for (int nt = 0; nt < 4; nt++) {
                const int n = nb + nt * 8 + gid;
                unsigned ba0 = f2tf32(fBa[swz(n, c0)]), ba1 = f2tf32(fBa[swz(n, c0 + 4)]);
                unsigned bc0 = f2tf32(fBc[swz(n, c0)]), bc1 = f2tf32(fBc[swz(n, c0 + 4)]);
#pragma unroll
                for (int mt = 0; mt < 2; mt++) {
                    mma8(accA[mt][nt], a[mt], ba0, ba1);
                    mma8(accC[mt][nt], a[mt], bc0, bc1);
                }
            }
        }
        __syncthreads();                               // reads done before refill
    }

    // split-K accumulate (on top of tA/tC baseline from k_init)
#pragma unroll
    for (int mt = 0; mt < 2; mt++)
#pragma unroll
        for (int nt = 0; nt < 4; nt++) {
            const int r0 = mb + mt * 16 + gid;
            const int c0 = nh * 64 + nb + nt * 8 + tig * 2;
            atomicAdd(&g_A2[r0 * DD + c0],           accA[mt][nt][0]);
            atomicAdd(&g_A2[r0 * DD + c0 + 1],       accA[mt][nt][1]);
            atomicAdd(&g_A2[(r0 + 8) * DD + c0],     accA[mt][nt][2]);
            atomicAdd(&g_A2[(r0 + 8) * DD + c0 + 1], accA[mt][nt][3]);
            atomicAdd(&g_C2[r0 * DD + c0],           accC[mt][nt][0]);
            atomicAdd(&g_C2[r0 * DD + c0 + 1],       accC[mt][nt][1]);
            atomicAdd(&g_C2[(r0 + 8) * DD + c0],     accC[mt][nt][2]);
            atomicAdd(&g_C2[(r0 + 8) * DD + c0 + 1], accC[mt][nt][3]);
        }
}

// ---------------- 3 hops, single block, At register-cached ----------------
__global__ void __launch_bounds__(512) k_hops() {
    __shared__ float sqd[DD];
    __shared__ float sP[256];
    __shared__ float sred[512];
    const int tid = threadIdx.x, lane = tid & 31, w = tid >> 5;
    const int mbase = w * 13;                 // warp-owned A rows (13 each)

    float ra[13][4];
#pragma unroll
    for (int i = 0; i < 13; i++) {
        const int m = mbase + i;
#pragma unroll
        for (int k = 0; k < 4; k++)
            ra[i][k] = (m < MM) ? g_A2[m * DD + lane + 32 * k] : 0.f;
    }
    if (tid < DD) sqd[tid] = g_qd[tid];
    __syncthreads();

    for (int h = 0; h < HOPS; h++) {
        float q0 = sqd[lane], q1 = sqd[lane + 32], q2 = sqd[lane + 64], q3 = sqd[lane + 96];
#pragma unroll
        for (int i = 0; i < 13; i++) {
            const int m = mbase + i;
            float acc = ra[i][0] * q0 + ra[i][1] * q1 + ra[i][2] * q2 + ra[i][3] * q3;
            acc = warp_sum(acc);
            if (lane == 0 && m < MM) sP[m] = acc;
        }
        __syncthreads();
        sred[tid] = (tid < MM) ? sP[tid] : -3.4e38f;
        __syncthreads();
        for (int s = 256; s >= 1; s >>= 1) {
            if (tid < s) sred[tid] = fmaxf(sred[tid], sred[tid + s]);
            __syncthreads();
        }
        float mx = sred[0];
        __syncthreads();
        float e = (tid < MM) ? __expf(sP[tid] - mx) : 0.f;
        sred[tid] = e;
        __syncthreads();
        for (int s = 256; s >= 1; s >>= 1) {
            if (tid < s) sred[tid] += sred[tid + s];
            __syncthreads();
        }
        float inv = 1.f / sred[0];
        __syncthreads();
        if (tid < MM) sP[tid] = e * inv;
        __syncthreads();
        {
            const int q = tid >> 7, d = tid & 127;
            float part = 0.f;
#pragma unroll 10
            for (int m = q * 50; m < q * 50 + 50; m++)
                part += sP[m] * g_C2[m * DD + d];
            sred[tid] = part;
            __syncthreads();
            float o = 0.f;
            if (q == 0)
                o = sqd[d] + sred[d] + sred[d + 128] + sred[d + 256] + sred[d + 384];
            __syncthreads();
            if (q == 0) sqd[d] = o;
            __syncthreads();
        }
    }
    if (tid < DD) g_qd[tid] = sqd[tid];
}

// ---------------- out[v] = o . Wout[v] ----------------
__global__ void __launch_bounds__(256) k_out(
    const float* __restrict__ Wout, float* __restrict__ out) {
    const int lane = threadIdx.x & 31;
    const int gw = (blockIdx.x * 256 + threadIdx.x) >> 5;
    const int nw = (gridDim.x * 256) >> 5;
    float4 qv = *(const float4*)(&g_qd[lane * 4]);
    for (int r = gw; r < VV; r += nw) {
        float4 wv = ((const float4*)(Wout + (size_t)r * DD))[lane];
        float acc = qv.x * wv.x + qv.y * wv.y + qv.z * wv.z + qv.w * wv.w;
        acc = warp_sum(acc);
        if (lane == 0) out[r] = acc;
    }
}

extern "C" void kernel_launch(void* const* d_in, const int* in_sizes, int n_in,
                              void* d_out, int out_size) {
    const float* question = (const float*)d_in[0];
    const float* memory   = (const float*)d_in[1];
    const float* Wa       = (const float*)d_in[2];
    const float* Wb       = (const float*)d_in[3];
    const float* Wc       = (const float*)d_in[4];
    const float* Wout     = (const float*)d_in[5];
    const float* tA       = (const float*)d_in[6];
    const float* tC       = (const float*)d_in[7];
    float* out = (float*)d_out;

    // idempotent opt-in for 96KB dynamic smem (no static guard)
    cudaFuncSetAttribute(k_gemm, cudaFuncAttributeMaxDynamicSharedMemorySize, GSMEM);

    k_init<<<32, 1024>>>(tA, tC);
    k_gemm<<<dim3(NKS, 2), 512, GSMEM>>>(memory, Wa, Wc);
    k_quesd<<<DD * 2, 256>>>(Wb, question);
    k_hops<<<1, 512>>>();
    k_out<<<592, 256>>>(Wout, out);
}